// round 1
// baseline (speedup 1.0000x reference)
#include <cuda_runtime.h>
#include <math.h>

#define N_NODES 16384
#define N_EDGES 131072
#define TE 128           // edges per MLP CTA

// ---------------- scratch (static device arrays: allocation-guard safe) ----
__device__ int   g_counts[N_NODES];
__device__ int   g_cursor[N_NODES];
__device__ int   g_offsets[N_NODES + 1];
__device__ int   g_edge[N_EDGES];
__device__ float g_w[(size_t)N_EDGES * 384];

// ---------------- CSR build ------------------------------------------------
__global__ void k_zero() {
    int i = blockIdx.x * blockDim.x + threadIdx.x;
    if (i < N_NODES) g_counts[i] = 0;
}

__global__ void k_hist(const int* __restrict__ recv) {
    int e = blockIdx.x * blockDim.x + threadIdx.x;
    if (e < N_EDGES) atomicAdd(&g_counts[recv[e]], 1);
}

// single CTA, 1024 threads, 16 counts/thread
__global__ void k_scan() {
    __shared__ int part[1024];
    int t = threadIdx.x;
    int base = t * 16;
    int loc[16];
    int sum = 0;
#pragma unroll
    for (int i = 0; i < 16; i++) { loc[i] = g_counts[base + i]; sum += loc[i]; }
    part[t] = sum;
    __syncthreads();
    for (int off = 1; off < 1024; off <<= 1) {
        int add = (t >= off) ? part[t - off] : 0;
        __syncthreads();
        part[t] += add;
        __syncthreads();
    }
    int run = part[t] - sum;   // exclusive base for this chunk
#pragma unroll
    for (int i = 0; i < 16; i++) {
        g_offsets[base + i] = run;
        run += loc[i];
        g_cursor[base + i] = 0;
    }
    if (t == 1023) g_offsets[N_NODES] = run;
}

__global__ void k_scatter(const int* __restrict__ recv) {
    int e = blockIdx.x * blockDim.x + threadIdx.x;
    if (e < N_EDGES) {
        int r = recv[e];
        int pos = g_offsets[r] + atomicAdd(&g_cursor[r], 1);
        g_edge[pos] = e;
    }
}

// ---------------- per-edge MLP: w = silu(silu(r@W1/s8)@W2/8)@W3 * SC -------
// SC folds /sqrt(HIDDEN) and the final /sqrt(AVG_NUM_NEIGHBORS)
#define SCALE_H1 0.35355339059327373f   // 1/sqrt(8)
#define SCALE_H2 0.125f                 // 1/sqrt(64)
#define SCALE_W  0.04419417382415922f   // 0.125 * (1/sqrt(8))

__device__ __forceinline__ float silu_f(float x) {
    float sg = 1.0f / (1.0f + __expf(-x));
    return x * sg;
}

__global__ void __launch_bounds__(256) k_mlp(
    const float* __restrict__ radial,
    const float* __restrict__ w1,
    const float* __restrict__ w2,
    const float* __restrict__ w3)
{
    extern __shared__ float sm[];
    float* sw1 = sm;                 //  512  : w1 [k][j]
    float* sw2 = sw1 + 512;          // 4096  : w2 [k][j]
    float* sR  = sw2 + 4096;         // 1024  : radial [e][k]
    float* sH1 = sR  + 1024;         // 8192  : H1 [k][e]
    float* sH2 = sH1 + 8192;         // 8192  : H2 [k][e]
    float* sw3 = sH2 + 8192;         // 4096  : w3 chunk [k][j]

    int t = threadIdx.x;                 // 256 threads
    int ebase = blockIdx.x * TE;

    for (int i = t; i < 512;  i += 256) sw1[i] = w1[i];
    for (int i = t; i < 4096; i += 256) sw2[i] = w2[i];
    for (int i = t; i < TE * 8; i += 256) sR[i] = radial[(size_t)ebase * 8 + i];
    __syncthreads();

    // ---- H1 = silu(R @ W1 * SCALE_H1) ----
    for (int idx = t; idx < TE * 64; idx += 256) {
        int j = idx & 63, e = idx >> 6;
        float acc = 0.f;
#pragma unroll
        for (int k = 0; k < 8; k++) acc = fmaf(sR[e * 8 + k], sw1[k * 64 + j], acc);
        sH1[j * TE + e] = silu_f(acc * SCALE_H1);
    }
    __syncthreads();

    int jb = t & 7, eb = t >> 3;     // eb: 0..31, jb: 0..7
    int e4 = eb * 4, j0 = jb * 8;    // thread tile: 4 edges x 8 cols

    // ---- H2 = silu(H1 @ W2 * SCALE_H2) ----
    {
        float acc[4][8];
#pragma unroll
        for (int a = 0; a < 4; a++)
#pragma unroll
            for (int b = 0; b < 8; b++) acc[a][b] = 0.f;
#pragma unroll 4
        for (int k = 0; k < 64; k++) {
            float4 av = *(const float4*)&sH1[k * TE + e4];
            float4 b0 = *(const float4*)&sw2[k * 64 + j0];
            float4 b1 = *(const float4*)&sw2[k * 64 + j0 + 4];
            float aa[4] = {av.x, av.y, av.z, av.w};
            float bb[8] = {b0.x, b0.y, b0.z, b0.w, b1.x, b1.y, b1.z, b1.w};
#pragma unroll
            for (int a = 0; a < 4; a++)
#pragma unroll
                for (int b = 0; b < 8; b++) acc[a][b] = fmaf(aa[a], bb[b], acc[a][b]);
        }
#pragma unroll
        for (int b = 0; b < 8; b++) {
            float v0 = silu_f(acc[0][b] * SCALE_H2);
            float v1 = silu_f(acc[1][b] * SCALE_H2);
            float v2 = silu_f(acc[2][b] * SCALE_H2);
            float v3 = silu_f(acc[3][b] * SCALE_H2);
            *(float4*)&sH2[(j0 + b) * TE + e4] = make_float4(v0, v1, v2, v3);
        }
    }
    __syncthreads();

    // ---- W = H2 @ W3 * SCALE_W, 6 chunks of 64 output cols ----
    for (int c = 0; c < 6; c++) {
        for (int i = t; i < 4096; i += 256) {
            int k = i >> 6, j = i & 63;
            sw3[i] = w3[k * 384 + c * 64 + j];
        }
        __syncthreads();

        float acc[4][8];
#pragma unroll
        for (int a = 0; a < 4; a++)
#pragma unroll
            for (int b = 0; b < 8; b++) acc[a][b] = 0.f;
#pragma unroll 4
        for (int k = 0; k < 64; k++) {
            float4 av = *(const float4*)&sH2[k * TE + e4];
            float4 b0 = *(const float4*)&sw3[k * 64 + j0];
            float4 b1 = *(const float4*)&sw3[k * 64 + j0 + 4];
            float aa[4] = {av.x, av.y, av.z, av.w};
            float bb[8] = {b0.x, b0.y, b0.z, b0.w, b1.x, b1.y, b1.z, b1.w};
#pragma unroll
            for (int a = 0; a < 4; a++)
#pragma unroll
                for (int b = 0; b < 8; b++) acc[a][b] = fmaf(aa[a], bb[b], acc[a][b]);
        }
#pragma unroll
        for (int a = 0; a < 4; a++) {
            size_t e = (size_t)(ebase + e4 + a);
            float* dst = g_w + e * 384 + c * 64 + j0;
            *(float4*)(dst)     = make_float4(acc[a][0] * SCALE_W, acc[a][1] * SCALE_W,
                                              acc[a][2] * SCALE_W, acc[a][3] * SCALE_W);
            *(float4*)(dst + 4) = make_float4(acc[a][4] * SCALE_W, acc[a][5] * SCALE_W,
                                              acc[a][6] * SCALE_W, acc[a][7] * SCALE_W);
        }
        __syncthreads();
    }
}

// ---------------- gather / tensor-product / accumulate ---------------------
// warp per receiver node; lane handles m0 = 2*lane and m0+1
#define INV_SQRT3 0.57735026918962576f

__global__ void __launch_bounds__(256) k_gather(
    const float* __restrict__ nf,
    const float* __restrict__ ef,
    const int*   __restrict__ send,
    float*       __restrict__ out)
{
    int gw = (blockIdx.x * blockDim.x + threadIdx.x) >> 5;
    int lane = threadIdx.x & 31;
    if (gw >= N_NODES) return;

    int beg = g_offsets[gw], end = g_offsets[gw + 1];
    int m0 = lane * 2;

    float s0a = 0.f, s0b = 0.f, s1a = 0.f, s1b = 0.f, s2a = 0.f, s2b = 0.f;
    float v0a0=0.f,v0a1=0.f,v0a2=0.f, v0b0=0.f,v0b1=0.f,v0b2=0.f;
    float v1a0=0.f,v1a1=0.f,v1a2=0.f, v1b0=0.f,v1b1=0.f,v1b2=0.f;
    float v2a0=0.f,v2a1=0.f,v2a2=0.f, v2b0=0.f,v2b1=0.f,v2b2=0.f;

    for (int p = beg; p < end; p++) {
        int e = g_edge[p];
        int s = send[e];
        const float* row = nf + (size_t)s * 256;
        float4 efv = *(const float4*)(ef + (size_t)e * 4);
        float es = efv.x, e0 = efv.y, e1 = efv.z, e2 = efv.w;

        float2 se = *(const float2*)(row + m0);
        float2 va = *(const float2*)(row + 64 + 3 * m0);
        float2 vb = *(const float2*)(row + 66 + 3 * m0);
        float2 vc = *(const float2*)(row + 68 + 3 * m0);

        const float* wr = g_w + (size_t)e * 384;
        float2 w0 = *(const float2*)(wr + m0);
        float2 w1 = *(const float2*)(wr + 64 + m0);
        float2 w2 = *(const float2*)(wr + 128 + m0);
        float2 w3 = *(const float2*)(wr + 192 + m0);
        float2 w4 = *(const float2*)(wr + 256 + m0);
        float2 w5 = *(const float2*)(wr + 320 + m0);

        // m = m0
        {
            float S = se.x, V0 = va.x, V1 = va.y, V2 = vb.x;
            float Ses = S * es;
            s0a = fmaf(S, w0.x, s0a);
            s1a = fmaf(Ses, w1.x, s1a);
            float dot = fmaf(V0, e0, fmaf(V1, e1, V2 * e2));
            s2a = fmaf(dot * INV_SQRT3, w2.x, s2a);
            v0a0 = fmaf(V0, w3.x, v0a0); v0a1 = fmaf(V1, w3.x, v0a1); v0a2 = fmaf(V2, w3.x, v0a2);
            v1a0 = fmaf(Ses == Ses ? S * e0 : 0.f, w4.x, v1a0);  // S*e0
            v1a1 = fmaf(S * e1, w4.x, v1a1);
            v1a2 = fmaf(S * e2, w4.x, v1a2);
            v2a0 = fmaf(V0 * es, w5.x, v2a0); v2a1 = fmaf(V1 * es, w5.x, v2a1); v2a2 = fmaf(V2 * es, w5.x, v2a2);
        }
        // m = m0 + 1
        {
            float S = se.y, V0 = vb.y, V1 = vc.x, V2 = vc.y;
            float Ses = S * es;
            s0b = fmaf(S, w0.y, s0b);
            s1b = fmaf(Ses, w1.y, s1b);
            float dot = fmaf(V0, e0, fmaf(V1, e1, V2 * e2));
            s2b = fmaf(dot * INV_SQRT3, w2.y, s2b);
            v0b0 = fmaf(V0, w3.y, v0b0); v0b1 = fmaf(V1, w3.y, v0b1); v0b2 = fmaf(V2, w3.y, v0b2);
            v1b0 = fmaf(S * e0, w4.y, v1b0); v1b1 = fmaf(S * e1, w4.y, v1b1); v1b2 = fmaf(S * e2, w4.y, v1b2);
            v2b0 = fmaf(V0 * es, w5.y, v2b0); v2b1 = fmaf(V1 * es, w5.y, v2b1); v2b2 = fmaf(V2 * es, w5.y, v2b2);
        }
    }

    float* o = out + (size_t)gw * 768;
    *(float2*)(o + m0)        = make_float2(s0a, s0b);
    *(float2*)(o + 64 + m0)   = make_float2(s1a, s1b);
    *(float2*)(o + 128 + m0)  = make_float2(s2a, s2b);

    // vec block b at columns 192 + (b*64 + m)*3 + xyz
    {
        int base = 192 + m0 * 3;
        *(float2*)(o + base)     = make_float2(v0a0, v0a1);
        *(float2*)(o + base + 2) = make_float2(v0a2, v0b0);
        *(float2*)(o + base + 4) = make_float2(v0b1, v0b2);
    }
    {
        int base = 192 + (64 + m0) * 3;
        *(float2*)(o + base)     = make_float2(v1a0, v1a1);
        *(float2*)(o + base + 2) = make_float2(v1a2, v1b0);
        *(float2*)(o + base + 4) = make_float2(v1b1, v1b2);
    }
    {
        int base = 192 + (128 + m0) * 3;
        *(float2*)(o + base)     = make_float2(v2a0, v2a1);
        *(float2*)(o + base + 2) = make_float2(v2a2, v2b0);
        *(float2*)(o + base + 4) = make_float2(v2b1, v2b2);
    }
}

// ---------------- launch ----------------------------------------------------
extern "C" void kernel_launch(void* const* d_in, const int* in_sizes, int n_in,
                              void* d_out, int out_size) {
    const float* nf   = (const float*)d_in[0];
    const float* ef   = (const float*)d_in[1];
    const float* rad  = (const float*)d_in[2];
    const float* w1   = (const float*)d_in[3];
    const float* w2   = (const float*)d_in[4];
    const float* w3   = (const float*)d_in[5];
    const int*   send = (const int*)d_in[6];
    const int*   recv = (const int*)d_in[7];
    float* out = (float*)d_out;

    const int smem_mlp = (512 + 4096 + 1024 + 8192 + 8192 + 4096) * 4; // 104448 B
    cudaFuncSetAttribute(k_mlp, cudaFuncAttributeMaxDynamicSharedMemorySize, smem_mlp);

    k_zero   <<<N_NODES / 256, 256>>>();
    k_hist   <<<N_EDGES / 256, 256>>>(recv);
    k_scan   <<<1, 1024>>>();
    k_scatter<<<N_EDGES / 256, 256>>>(recv);
    k_mlp    <<<N_EDGES / TE, 256, smem_mlp>>>(rad, w1, w2, w3);
    k_gather <<<(N_NODES * 32) / 256, 256>>>(nf, ef, send, out);
}